// round 6
// baseline (speedup 1.0000x reference)
#include <cuda_runtime.h>
#include <cuda_fp16.h>

#define NMAX 100000
#define EMAX 1600000
#define HDIM 64
#define NGROUP 8

// ---------------- device scratch (no allocation allowed) --------------------
__device__ __align__(256) __half g_h16[NMAX * HDIM];  // fp16 mirror for gathers
__device__ __align__(256) float g_hB[NMAX * HDIM];    // fp32 gather output
__device__ float g_s[NMAX];
__device__ float g_d[NMAX];
__device__ int   g_cnt[NMAX + 1];     // histogram, later scatter cursor
__device__ int   g_offs[NMAX + 1];    // CSR row offsets (by dst)
__device__ int   g_blksum[256];
__device__ int   g_csr[EMAX];         // src indices sorted by dst
__device__ float g_vnsum[NGROUP * HDIM];

// ---------------------------------------------------------------------------
// CSR build: zero -> histogram -> scanA -> scanC(+blk prefix) -> scatter
// ---------------------------------------------------------------------------
__global__ void zero_kernel(int N) {
    int i = blockIdx.x * blockDim.x + threadIdx.x;
    if (i <= N) g_cnt[i] = 0;
    if (i < NGROUP * HDIM) g_vnsum[i] = 0.f;
}

__global__ void hist_kernel(const int* __restrict__ ei, int E) {
    int e = blockIdx.x * blockDim.x + threadIdx.x;
    if (e < E) atomicAdd(&g_cnt[ei[E + e]], 1);
}

// per-block exclusive scan of g_cnt (1024 elements / block of 256 threads)
__global__ void scanA_kernel(int N) {
    __shared__ int wsum[8];
    int t = threadIdx.x;
    int base = blockIdx.x * 1024;
    int v[4]; int s = 0;
#pragma unroll
    for (int j = 0; j < 4; j++) {
        int idx = base + t * 4 + j;
        v[j] = (idx < N) ? g_cnt[idx] : 0;
        s += v[j];
    }
    int lane = t & 31, wid = t >> 5;
    int inc = s;
#pragma unroll
    for (int o = 1; o < 32; o <<= 1) {
        int y = __shfl_up_sync(0xffffffffu, inc, o);
        if (lane >= o) inc += y;
    }
    if (lane == 31) wsum[wid] = inc;
    __syncthreads();
    if (t < 8) {
        int x = wsum[t];
#pragma unroll
        for (int o = 1; o < 8; o <<= 1) {
            int y = __shfl_up_sync(0xffu, x, o);
            if (t >= o) x += y;
        }
        wsum[t] = x;
    }
    __syncthreads();
    int excl = inc - s + (wid > 0 ? wsum[wid - 1] : 0);
#pragma unroll
    for (int j = 0; j < 4; j++) {
        int idx = base + t * 4 + j;
        if (idx < N) g_offs[idx] = excl;
        excl += v[j];
    }
    if (t == 255) g_blksum[blockIdx.x] = wsum[7];
}

// adds cross-block prefix (computed in-kernel by warp 0) and finalizes offsets
__global__ void scanC_kernel(int N, int E) {
    __shared__ int sbase;
    int myblk = (blockIdx.x * 256) >> 10;   // which scanA block this belongs to
    if (threadIdx.x < 32) {
        int acc = 0;
        for (int j = threadIdx.x; j < myblk; j += 32) acc += g_blksum[j];
#pragma unroll
        for (int o = 16; o >= 1; o >>= 1) acc += __shfl_xor_sync(0xffffffffu, acc, o);
        if (threadIdx.x == 0) sbase = acc;
    }
    __syncthreads();
    int i = blockIdx.x * 256 + threadIdx.x;
    if (i < N) {
        int o = g_offs[i] + sbase;
        g_offs[i] = o;
        g_cnt[i] = o;   // scatter cursor
    }
    if (i == 0) g_offs[N] = E;
}

__global__ void scatter_kernel(const int* __restrict__ ei, int E) {
    int e = blockIdx.x * blockDim.x + threadIdx.x;
    if (e >= E) return;
    int src = ei[e];
    int dst = ei[E + e];
    int pos = atomicAdd(&g_cnt[dst], 1);
    g_csr[pos] = src;
}

// ---------------------------------------------------------------------------
// Layer 0 linear: h = x(N,3) @ W0(3,64) -> g_h16; also s = h.as, d = h.ad
// ---------------------------------------------------------------------------
__global__ void lin0_kernel(const float* __restrict__ x,
                            const float* __restrict__ W0,
                            const float* __restrict__ as0,
                            const float* __restrict__ ad0, int N) {
    __shared__ float Ws[3 * 64];
    __shared__ float hs[64][65];
    int t = threadIdx.x;
    int c = t & 63, r = t >> 6;
    int n0 = blockIdx.x * 64;
    if (t < 192) Ws[t] = W0[t];
    __syncthreads();
#pragma unroll
    for (int i = 0; i < 16; i++) {
        int nl = r * 16 + i;
        int n = n0 + nl;
        float acc = 0.f;
        if (n < N) {
            float x0 = x[n * 3 + 0], x1 = x[n * 3 + 1], x2 = x[n * 3 + 2];
            acc = x0 * Ws[c] + x1 * Ws[64 + c] + x2 * Ws[128 + c];
            g_h16[n * 64 + c] = __float2half_rn(acc);
        }
        hs[nl][c] = acc;
    }
    __syncthreads();
    if (t < 64) {
        int n = n0 + t;
        if (n < N) {
            float sv = 0.f, dv = 0.f;
#pragma unroll
            for (int k = 0; k < 64; k++) {
                float hv = hs[t][k];
                sv += hv * as0[k];
                dv += hv * ad0[k];
            }
            g_s[n] = sv;
            g_d[n] = dv;
        }
    }
}

// ---------------------------------------------------------------------------
// Gather attention pass (g_h16 -> g_hB): ONE 16-LANE HALF-WARP PER NODE.
// Each lane covers 8 bytes (4 halves) of the 128-B row, so one warp serves
// 2 nodes: every LDS/LDG instruction handles 2 edges. Chunks of 16 edges
// (= mean degree) for the p-staging. Warp-uniform chunk-loop trip count
// (max over the 2 halves) keeps __syncwarp legal; inner loop is predicated.
// (max-shift skipped: softmax shift-invariant, logits are O(0.1))
// ---------------------------------------------------------------------------
__global__ void gather_kernel(const float* __restrict__ bias, int N) {
    __shared__ int2 stage[16][16];   // [half-warp in block][edge slot]
    int hwId = (blockIdx.x * blockDim.x + threadIdx.x) >> 4;
    int l  = threadIdx.x & 15;       // lane within half-warp
    int sh = threadIdx.x >> 4;       // half-warp index in block (0..15)
    const unsigned FULL = 0xffffffffu;
    bool valid = hwId < N;
    int dst = valid ? hwId : 0;
    float dv = g_d[dst];
    float lg = g_s[dst] + dv;
    lg = lg > 0.f ? lg : 0.2f * lg;
    float pself = __expf(lg);
    uint2 hraw = *(const uint2*)(g_h16 + dst * 64 + l * 4);
    float2 hA = __half22float2(*(__half2*)&hraw.x);
    float2 hB = __half22float2(*(__half2*)&hraw.y);
    float a0 = pself * hA.x, a1 = pself * hA.y;
    float a2 = pself * hB.x, a3 = pself * hB.y;
    float denl = (l == 0) ? pself : 0.f;
    int e0 = valid ? g_offs[dst] : 0;
    int e1 = valid ? g_offs[dst + 1] : 0;
    int nch = (e1 - e0 + 15) >> 4;
    int nchO = __shfl_xor_sync(FULL, nch, 16);
    int nchU = nch > nchO ? nch : nchO;
    for (int c = 0; c < nchU; c++) {
        int base = e0 + (c << 4);
        int m = e1 - base;
        if (m > 16) m = 16;
        if (m < 0) m = 0;
        int idx = dst; float pv = 0.f;
        if (l < m) {
            idx = g_csr[base + l];
            float sv = g_s[idx];
            float ll = sv + dv;
            ll = ll > 0.f ? ll : 0.2f * ll;
            pv = __expf(ll);
        }
        denl += pv;
        stage[sh][l] = make_int2(idx, __float_as_int(pv));
        __syncwarp(FULL);
        int j = 0;
        for (; j + 3 < m; j += 4) {
            int2 v0 = stage[sh][j],     v1 = stage[sh][j + 1];
            int2 v2 = stage[sh][j + 2], v3 = stage[sh][j + 3];
            uint2 r0 = *(const uint2*)(g_h16 + v0.x * 64 + l * 4);
            uint2 r1 = *(const uint2*)(g_h16 + v1.x * 64 + l * 4);
            uint2 r2 = *(const uint2*)(g_h16 + v2.x * 64 + l * 4);
            uint2 r3 = *(const uint2*)(g_h16 + v3.x * 64 + l * 4);
            float p0 = __int_as_float(v0.y), p1 = __int_as_float(v1.y);
            float p2 = __int_as_float(v2.y), p3 = __int_as_float(v3.y);
            float2 fA, fB;
            fA = __half22float2(*(__half2*)&r0.x); fB = __half22float2(*(__half2*)&r0.y);
            a0 += p0 * fA.x; a1 += p0 * fA.y; a2 += p0 * fB.x; a3 += p0 * fB.y;
            fA = __half22float2(*(__half2*)&r1.x); fB = __half22float2(*(__half2*)&r1.y);
            a0 += p1 * fA.x; a1 += p1 * fA.y; a2 += p1 * fB.x; a3 += p1 * fB.y;
            fA = __half22float2(*(__half2*)&r2.x); fB = __half22float2(*(__half2*)&r2.y);
            a0 += p2 * fA.x; a1 += p2 * fA.y; a2 += p2 * fB.x; a3 += p2 * fB.y;
            fA = __half22float2(*(__half2*)&r3.x); fB = __half22float2(*(__half2*)&r3.y);
            a0 += p3 * fA.x; a1 += p3 * fA.y; a2 += p3 * fB.x; a3 += p3 * fB.y;
        }
        for (; j < m; j++) {
            int2 v = stage[sh][j];
            uint2 r = *(const uint2*)(g_h16 + v.x * 64 + l * 4);
            float p = __int_as_float(v.y);
            float2 fA = __half22float2(*(__half2*)&r.x);
            float2 fB = __half22float2(*(__half2*)&r.y);
            a0 += p * fA.x; a1 += p * fA.y; a2 += p * fB.x; a3 += p * fB.y;
        }
        __syncwarp(FULL);
    }
#pragma unroll
    for (int o = 8; o >= 1; o >>= 1) denl += __shfl_xor_sync(FULL, denl, o, 16);
    if (valid) {
        float inv = 1.f / denl;
        float o0 = a0 * inv + bias[l * 4 + 0];
        float o1 = a1 * inv + bias[l * 4 + 1];
        float o2 = a2 * inv + bias[l * 4 + 2];
        float o3 = a3 * inv + bias[l * 4 + 3];
        o0 = o0 > 0.f ? o0 : 0.01f * o0;
        o1 = o1 > 0.f ? o1 : 0.01f * o1;
        o2 = o2 > 0.f ? o2 : 0.01f * o2;
        o3 = o3 > 0.f ? o3 : 0.01f * o3;
        *(float4*)(g_hB + dst * 64 + l * 4) = make_float4(o0, o1, o2, o3);
    }
}

// ---------------------------------------------------------------------------
// GEMM (g_hB -> g_h16): h = x(128-node tile,64) @ W(64,64), 8x4 register tile;
// fused s/d attention dots via 16-lane shuffle reduction.
// Block: 256 threads = 16 node-groups x 16 col-groups.
// ---------------------------------------------------------------------------
__global__ void fin_lin_kernel(const float* __restrict__ W,
                               const float* __restrict__ avs,
                               const float* __restrict__ avd, int N) {
    __shared__ float xs[128][65];
    __shared__ float Ws[64][64];
    int t = threadIdx.x;
    int n0 = blockIdx.x * 128;
#pragma unroll
    for (int j = 0; j < 16; j++) {
        int idx = j * 256 + t;
        Ws[idx >> 6][idx & 63] = W[idx];
    }
#pragma unroll
    for (int j = 0; j < 32; j++) {
        int idx = j * 256 + t;
        int nl = idx >> 6, c = idx & 63;
        int n = n0 + nl;
        xs[nl][c] = (n < N) ? g_hB[n * 64 + c] : 0.f;
    }
    __syncthreads();
    int cg = t & 15, ng = t >> 4;
    float acc[8][4];
#pragma unroll
    for (int i = 0; i < 8; i++)
#pragma unroll
        for (int j = 0; j < 4; j++) acc[i][j] = 0.f;
#pragma unroll 8
    for (int k = 0; k < 64; k++) {
        float4 w4 = *(const float4*)&Ws[k][cg * 4];
#pragma unroll
        for (int i = 0; i < 8; i++) {
            float xv = xs[ng * 8 + i][k];
            acc[i][0] += xv * w4.x;
            acc[i][1] += xv * w4.y;
            acc[i][2] += xv * w4.z;
            acc[i][3] += xv * w4.w;
        }
    }
    // store fp16 mirror (only consumer is the next gather pass)
#pragma unroll
    for (int i = 0; i < 8; i++) {
        int n = n0 + ng * 8 + i;
        if (n < N) {
            __half2* hp = (__half2*)(g_h16 + n * 64 + cg * 4);
            hp[0] = __floats2half2_rn(acc[i][0], acc[i][1]);
            hp[1] = __floats2half2_rn(acc[i][2], acc[i][3]);
        }
    }
    // fused s/d dots: partials over this thread's 4 cols, reduce over 16 lanes
    float a0 = avs[cg * 4], a1 = avs[cg * 4 + 1], a2 = avs[cg * 4 + 2], a3 = avs[cg * 4 + 3];
    float d0 = avd[cg * 4], d1 = avd[cg * 4 + 1], d2 = avd[cg * 4 + 2], d3 = avd[cg * 4 + 3];
#pragma unroll
    for (int i = 0; i < 8; i++) {
        float ps = acc[i][0] * a0 + acc[i][1] * a1 + acc[i][2] * a2 + acc[i][3] * a3;
        float pd = acc[i][0] * d0 + acc[i][1] * d1 + acc[i][2] * d2 + acc[i][3] * d3;
#pragma unroll
        for (int o = 8; o >= 1; o >>= 1) {
            ps += __shfl_xor_sync(0xffffffffu, ps, o, 16);
            pd += __shfl_xor_sync(0xffffffffu, pd, o, 16);
        }
        if (cg == 0) {
            int n = n0 + ng * 8 + i;
            if (n < N) { g_s[n] = ps; g_d[n] = pd; }
        }
    }
}

// ---------------------------------------------------------------------------
// Final stage (reads g_hB): out1 = h @ out_w + out_b (4x5 register tile);
// vn run-length pooling (batch sorted). Block: 128 nodes, 128 threads.
// ---------------------------------------------------------------------------
__global__ void fin_last_kernel(const float* __restrict__ out_w,
                                const float* __restrict__ out_b,
                                const int* __restrict__ batch,
                                float* __restrict__ out1, int N) {
    __shared__ float hs[128][65];
    __shared__ float ow[64][20];
    __shared__ float ob[20];
    __shared__ int bsh[128];
    int t = threadIdx.x;
    int n0 = blockIdx.x * 128;
    for (int idx = t; idx < 64 * 20; idx += 128) ow[idx / 20][idx % 20] = out_w[idx];
    if (t < 20) ob[t] = out_b[t];
#pragma unroll
    for (int j = 0; j < 64; j++) {
        int idx = j * 128 + t;
        int nl = idx >> 6, c = idx & 63;
        int n = n0 + nl;
        hs[nl][c] = (n < N) ? g_hB[n * 64 + c] : 0.f;
    }
    {
        int n = n0 + t;
        bsh[t] = (n < N) ? batch[n] : -1;
    }
    __syncthreads();
    int ngq = t >> 2, cgq = t & 3;   // 32 node groups x 4 col groups
    float acc[4][5];
#pragma unroll
    for (int i = 0; i < 4; i++)
#pragma unroll
        for (int j = 0; j < 5; j++) acc[i][j] = ob[cgq * 5 + j];
#pragma unroll 8
    for (int k = 0; k < 64; k++) {
        float wv[5];
#pragma unroll
        for (int j = 0; j < 5; j++) wv[j] = ow[k][cgq * 5 + j];
#pragma unroll
        for (int i = 0; i < 4; i++) {
            float hv = hs[ngq * 4 + i][k];
#pragma unroll
            for (int j = 0; j < 5; j++) acc[i][j] += hv * wv[j];
        }
    }
#pragma unroll
    for (int i = 0; i < 4; i++) {
        int n = n0 + ngq * 4 + i;
        if (n < N) {
#pragma unroll
            for (int j = 0; j < 5; j++) out1[n * 20 + cgq * 5 + j] = acc[i][j];
        }
    }
    // vn pooling: threads 0..63 own one column each, run-length over block
    if (t < 64) {
        int nend = N - n0;
        if (nend > 128) nend = 128;
        if (nend > 0) {
            int curg = bsh[0];
            float run = 0.f;
            for (int nl = 0; nl < nend; nl++) {
                int g = bsh[nl];
                if (g != curg) {
                    atomicAdd(&g_vnsum[curg * 64 + t], run);
                    run = 0.f;
                    curg = g;
                }
                run += hs[nl][t];
            }
            atomicAdd(&g_vnsum[curg * 64 + t], run);
        }
    }
}

// ---------------------------------------------------------------------------
// Virtual-node MLP head: 4 layers on [8,64] -> [8,20]. One block.
// ---------------------------------------------------------------------------
__global__ void vn_mlp_kernel(const float* __restrict__ vn_emb0,
                              const float* __restrict__ w1, const float* __restrict__ bb1,
                              const float* __restrict__ w2, const float* __restrict__ bb2,
                              const float* __restrict__ w3, const float* __restrict__ bb3,
                              const float* __restrict__ w4, const float* __restrict__ bb4,
                              float* __restrict__ outvn) {
    __shared__ float a[NGROUP][64], tmp[NGROUP][64];
    int t = threadIdx.x;  // 512
    int g = t >> 6, c = t & 63;
    a[g][c] = g_vnsum[g * 64 + c] + vn_emb0[c];
    __syncthreads();
    float s = bb1[c];
    for (int k = 0; k < 64; k++) s += a[g][k] * w1[k * 64 + c];
    tmp[g][c] = fmaxf(s, 0.f);
    __syncthreads();
    s = bb2[c];
    for (int k = 0; k < 64; k++) s += tmp[g][k] * w2[k * 64 + c];
    a[g][c] = fmaxf(s, 0.f);
    __syncthreads();
    s = bb3[c];
    for (int k = 0; k < 64; k++) s += a[g][k] * w3[k * 64 + c];
    tmp[g][c] = fmaxf(s, 0.f);
    __syncthreads();
    if (c < 20) {
        s = bb4[c];
        for (int k = 0; k < 64; k++) s += tmp[g][k] * w4[k * 20 + c];
        outvn[g * 20 + c] = fmaxf(s, 0.f);
    }
}

// ---------------------------------------------------------------------------
extern "C" void kernel_launch(void* const* d_in, const int* in_sizes, int n_in,
                              void* d_out, int out_size) {
    const float* x      = (const float*)d_in[0];
    const int*   ei     = (const int*)d_in[1];
    const int*   batch  = (const int*)d_in[2];
    const float* W0     = (const float*)d_in[3];
    const float* as0    = (const float*)d_in[4];
    const float* ad0    = (const float*)d_in[5];
    const float* b0     = (const float*)d_in[6];
    const float* W1     = (const float*)d_in[7];
    const float* as1    = (const float*)d_in[8];
    const float* ad1    = (const float*)d_in[9];
    const float* b1     = (const float*)d_in[10];
    const float* W2     = (const float*)d_in[11];
    const float* as2    = (const float*)d_in[12];
    const float* ad2    = (const float*)d_in[13];
    const float* b2     = (const float*)d_in[14];
    const float* vn_emb0= (const float*)d_in[15];
    const float* m1_w1  = (const float*)d_in[16];
    const float* m1_b1  = (const float*)d_in[17];
    const float* m1_w2  = (const float*)d_in[18];
    const float* m1_b2  = (const float*)d_in[19];
    const float* mf_w1  = (const float*)d_in[20];
    const float* mf_b1  = (const float*)d_in[21];
    const float* mf_w2  = (const float*)d_in[22];
    const float* mf_b2  = (const float*)d_in[23];
    const float* out_w  = (const float*)d_in[24];
    const float* out_b  = (const float*)d_in[25];

    int N = in_sizes[0] / 3;
    int E = in_sizes[1] / 2;
    float* out1 = (float*)d_out;
    float* outvn = out1 + (long long)N * 20;

    int nblk64  = (N + 63) / 64;
    int nblk128 = (N + 127) / 128;
    int eblk    = (E + 255) / 256;
    int NB      = (N + 1023) / 1024;
    int gblk    = (N * 16 + 255) / 256;   // one 16-lane half-warp per node

    // CSR build (graph shared by all 3 layers)
    zero_kernel<<<(N + 256) / 256, 256>>>(N);
    hist_kernel<<<eblk, 256>>>(ei, E);
    scanA_kernel<<<NB, 256>>>(N);
    scanC_kernel<<<(N + 255) / 256, 256>>>(N, E);
    scatter_kernel<<<eblk, 256>>>(ei, E);

    // GNN layers (ping-pong: lin0 -> h16, gather h16->B, fin_lin B->h16)
    lin0_kernel<<<nblk64, 256>>>(x, W0, as0, ad0, N);
    gather_kernel<<<gblk, 256>>>(b0, N);
    fin_lin_kernel<<<nblk128, 256>>>(W1, as1, ad1, N);
    gather_kernel<<<gblk, 256>>>(b1, N);
    fin_lin_kernel<<<nblk128, 256>>>(W2, as2, ad2, N);
    gather_kernel<<<gblk, 256>>>(b2, N);

    // heads (read g_hB)
    fin_last_kernel<<<nblk128, 128>>>(out_w, out_b, batch, out1, N);
    vn_mlp_kernel<<<1, 512>>>(vn_emb0, m1_w1, m1_b1, m1_w2, m1_b2,
                              mf_w1, mf_b1, mf_w2, mf_b2, outvn);
}

// round 7
// speedup vs baseline: 1.3724x; 1.3724x over previous
#include <cuda_runtime.h>
#include <cuda_fp16.h>

#define NMAX 100000
#define EMAX 1600000
#define HDIM 64
#define NGROUP 8

// ---------------- device scratch (no allocation allowed) --------------------
__device__ __align__(256) __half g_h16[NMAX * HDIM];  // fp16 mirror for gathers
__device__ __align__(256) float g_hB[NMAX * HDIM];    // fp32 gather output
__device__ float g_s[NMAX];
__device__ float g_d[NMAX];
__device__ int   g_cnt[NMAX + 1];     // histogram, later scatter cursor
__device__ int   g_offs[NMAX + 1];    // CSR row offsets (by dst)
__device__ int   g_blksum[256];
__device__ int   g_csr[EMAX];         // src indices sorted by dst
__device__ float g_vnsum[NGROUP * HDIM];

// ---------------------------------------------------------------------------
// CSR build: zero -> histogram -> scanA -> scanC(+blk prefix) -> scatter
// ---------------------------------------------------------------------------
__global__ void zero_kernel(int N) {
    int i = blockIdx.x * blockDim.x + threadIdx.x;
    if (i <= N) g_cnt[i] = 0;
    if (i < NGROUP * HDIM) g_vnsum[i] = 0.f;
}

__global__ void hist_kernel(const int* __restrict__ ei, int E) {
    int e = blockIdx.x * blockDim.x + threadIdx.x;
    if (e < E) atomicAdd(&g_cnt[ei[E + e]], 1);
}

// per-block exclusive scan of g_cnt (1024 elements / block of 256 threads)
__global__ void scanA_kernel(int N) {
    __shared__ int wsum[8];
    int t = threadIdx.x;
    int base = blockIdx.x * 1024;
    int v[4]; int s = 0;
#pragma unroll
    for (int j = 0; j < 4; j++) {
        int idx = base + t * 4 + j;
        v[j] = (idx < N) ? g_cnt[idx] : 0;
        s += v[j];
    }
    int lane = t & 31, wid = t >> 5;
    int inc = s;
#pragma unroll
    for (int o = 1; o < 32; o <<= 1) {
        int y = __shfl_up_sync(0xffffffffu, inc, o);
        if (lane >= o) inc += y;
    }
    if (lane == 31) wsum[wid] = inc;
    __syncthreads();
    if (t < 8) {
        int x = wsum[t];
#pragma unroll
        for (int o = 1; o < 8; o <<= 1) {
            int y = __shfl_up_sync(0xffu, x, o);
            if (t >= o) x += y;
        }
        wsum[t] = x;
    }
    __syncthreads();
    int excl = inc - s + (wid > 0 ? wsum[wid - 1] : 0);
#pragma unroll
    for (int j = 0; j < 4; j++) {
        int idx = base + t * 4 + j;
        if (idx < N) g_offs[idx] = excl;
        excl += v[j];
    }
    if (t == 255) g_blksum[blockIdx.x] = wsum[7];
}

// adds cross-block prefix (computed in-kernel by warp 0) and finalizes offsets
__global__ void scanC_kernel(int N, int E) {
    __shared__ int sbase;
    int myblk = (blockIdx.x * 256) >> 10;   // which scanA block this belongs to
    if (threadIdx.x < 32) {
        int acc = 0;
        for (int j = threadIdx.x; j < myblk; j += 32) acc += g_blksum[j];
#pragma unroll
        for (int o = 16; o >= 1; o >>= 1) acc += __shfl_xor_sync(0xffffffffu, acc, o);
        if (threadIdx.x == 0) sbase = acc;
    }
    __syncthreads();
    int i = blockIdx.x * 256 + threadIdx.x;
    if (i < N) {
        int o = g_offs[i] + sbase;
        g_offs[i] = o;
        g_cnt[i] = o;   // scatter cursor
    }
    if (i == 0) g_offs[N] = E;
}

__global__ void scatter_kernel(const int* __restrict__ ei, int E) {
    int e = blockIdx.x * blockDim.x + threadIdx.x;
    if (e >= E) return;
    int src = ei[e];
    int dst = ei[E + e];
    int pos = atomicAdd(&g_cnt[dst], 1);
    g_csr[pos] = src;
}

// ---------------------------------------------------------------------------
// Layer 0 linear: h = x(N,3) @ W0(3,64) -> g_h16; also s = h.as, d = h.ad
// ---------------------------------------------------------------------------
__global__ void lin0_kernel(const float* __restrict__ x,
                            const float* __restrict__ W0,
                            const float* __restrict__ as0,
                            const float* __restrict__ ad0, int N) {
    __shared__ float Ws[3 * 64];
    __shared__ float hs[64][65];
    int t = threadIdx.x;
    int c = t & 63, r = t >> 6;
    int n0 = blockIdx.x * 64;
    if (t < 192) Ws[t] = W0[t];
    __syncthreads();
#pragma unroll
    for (int i = 0; i < 16; i++) {
        int nl = r * 16 + i;
        int n = n0 + nl;
        float acc = 0.f;
        if (n < N) {
            float x0 = x[n * 3 + 0], x1 = x[n * 3 + 1], x2 = x[n * 3 + 2];
            acc = x0 * Ws[c] + x1 * Ws[64 + c] + x2 * Ws[128 + c];
            g_h16[n * 64 + c] = __float2half_rn(acc);
        }
        hs[nl][c] = acc;
    }
    __syncthreads();
    if (t < 64) {
        int n = n0 + t;
        if (n < N) {
            float sv = 0.f, dv = 0.f;
#pragma unroll
            for (int k = 0; k < 64; k++) {
                float hv = hs[t][k];
                sv += hv * as0[k];
                dv += hv * ad0[k];
            }
            g_s[n] = sv;
            g_d[n] = dv;
        }
    }
}

// ---------------------------------------------------------------------------
// Gather attention pass (g_h16 -> g_hB): one warp per dst node.
// Chunked: each lane computes p for ONE edge (1 coalesced csr LDG, 1 s LDG,
// 1 MUFU per 32 edges), stages (src,p) in smem; broadcast loop then does
// 1 LDS.64 + 1 LDG per edge, unrolled x8 with 2 independent FMA chains.
// Per-lane denom, one butterfly reduce at end.
// (max-shift skipped: softmax shift-invariant, logits are O(0.1))
// ---------------------------------------------------------------------------
__global__ void gather_kernel(const float* __restrict__ bias, int N) {
    __shared__ int2 stage[8][32];
    int w = (blockIdx.x * blockDim.x + threadIdx.x) >> 5;
    int lane = threadIdx.x & 31;
    int wl = threadIdx.x >> 5;
    if (w >= N) return;
    int dst = w;
    float dv = g_d[dst];
    // self loop
    float lg = g_s[dst] + dv;
    lg = lg > 0.f ? lg : 0.2f * lg;
    float pself = __expf(lg);
    float2 h2 = __half22float2(*(const __half2*)(g_h16 + dst * 64 + lane * 2));
    float ax0 = pself * h2.x, ay0 = pself * h2.y;
    float ax1 = 0.f, ay1 = 0.f;
    float denl = (lane == 0) ? pself : 0.f;
    int e0 = g_offs[dst], e1 = g_offs[dst + 1];
    for (int base = e0; base < e1; base += 32) {
        int cnt = e1 - base;
        if (cnt > 32) cnt = 32;
        int idx = 0;
        float pv = 0.f;
        if (lane < cnt) {
            idx = g_csr[base + lane];
            float sv = g_s[idx];
            float l = sv + dv;
            l = l > 0.f ? l : 0.2f * l;
            pv = __expf(l);
        }
        denl += pv;
        stage[wl][lane] = make_int2(idx, __float_as_int(pv));
        __syncwarp();
        int j = 0;
        for (; j + 7 < cnt; j += 8) {
            int2 v0 = stage[wl][j],     v1 = stage[wl][j + 1];
            int2 v2 = stage[wl][j + 2], v3 = stage[wl][j + 3];
            int2 v4 = stage[wl][j + 4], v5 = stage[wl][j + 5];
            int2 v6 = stage[wl][j + 6], v7 = stage[wl][j + 7];
            float2 f0 = __half22float2(*(const __half2*)(g_h16 + v0.x * 64 + lane * 2));
            float2 f1 = __half22float2(*(const __half2*)(g_h16 + v1.x * 64 + lane * 2));
            float2 f2 = __half22float2(*(const __half2*)(g_h16 + v2.x * 64 + lane * 2));
            float2 f3 = __half22float2(*(const __half2*)(g_h16 + v3.x * 64 + lane * 2));
            float2 f4 = __half22float2(*(const __half2*)(g_h16 + v4.x * 64 + lane * 2));
            float2 f5 = __half22float2(*(const __half2*)(g_h16 + v5.x * 64 + lane * 2));
            float2 f6 = __half22float2(*(const __half2*)(g_h16 + v6.x * 64 + lane * 2));
            float2 f7 = __half22float2(*(const __half2*)(g_h16 + v7.x * 64 + lane * 2));
            float p0 = __int_as_float(v0.y), p1 = __int_as_float(v1.y);
            float p2 = __int_as_float(v2.y), p3 = __int_as_float(v3.y);
            float p4 = __int_as_float(v4.y), p5 = __int_as_float(v5.y);
            float p6 = __int_as_float(v6.y), p7 = __int_as_float(v7.y);
            ax0 += p0 * f0.x + p2 * f2.x + p4 * f4.x + p6 * f6.x;
            ay0 += p0 * f0.y + p2 * f2.y + p4 * f4.y + p6 * f6.y;
            ax1 += p1 * f1.x + p3 * f3.x + p5 * f5.x + p7 * f7.x;
            ay1 += p1 * f1.y + p3 * f3.y + p5 * f5.y + p7 * f7.y;
        }
        for (; j + 1 < cnt; j += 2) {
            int2 va = stage[wl][j], vb = stage[wl][j + 1];
            float2 fa = __half22float2(*(const __half2*)(g_h16 + va.x * 64 + lane * 2));
            float2 fb = __half22float2(*(const __half2*)(g_h16 + vb.x * 64 + lane * 2));
            float pa = __int_as_float(va.y), pb = __int_as_float(vb.y);
            ax0 += pa * fa.x; ay0 += pa * fa.y;
            ax1 += pb * fb.x; ay1 += pb * fb.y;
        }
        if (j < cnt) {
            int2 v = stage[wl][j];
            float2 f = __half22float2(*(const __half2*)(g_h16 + v.x * 64 + lane * 2));
            float pj = __int_as_float(v.y);
            ax0 += pj * f.x;
            ay0 += pj * f.y;
        }
        __syncwarp();
    }
    float ax = ax0 + ax1, ay = ay0 + ay1;
#pragma unroll
    for (int o = 16; o >= 1; o >>= 1) denl += __shfl_xor_sync(0xffffffffu, denl, o);
    float inv = 1.f / denl;
    float ox = ax * inv + bias[lane * 2];
    float oy = ay * inv + bias[lane * 2 + 1];
    ox = ox > 0.f ? ox : 0.01f * ox;
    oy = oy > 0.f ? oy : 0.01f * oy;
    *(float2*)(g_hB + dst * 64 + lane * 2) = make_float2(ox, oy);
}

// ---------------------------------------------------------------------------
// GEMM (g_hB -> g_h16): h = x(128-node tile,64) @ W(64,64), 8x4 register tile;
// fused s/d attention dots via 16-lane shuffle reduction.
// Block: 256 threads = 16 node-groups x 16 col-groups.
// ---------------------------------------------------------------------------
__global__ void fin_lin_kernel(const float* __restrict__ W,
                               const float* __restrict__ avs,
                               const float* __restrict__ avd, int N) {
    __shared__ float xs[128][65];
    __shared__ float Ws[64][64];
    int t = threadIdx.x;
    int n0 = blockIdx.x * 128;
#pragma unroll
    for (int j = 0; j < 16; j++) {
        int idx = j * 256 + t;
        Ws[idx >> 6][idx & 63] = W[idx];
    }
#pragma unroll
    for (int j = 0; j < 32; j++) {
        int idx = j * 256 + t;
        int nl = idx >> 6, c = idx & 63;
        int n = n0 + nl;
        xs[nl][c] = (n < N) ? g_hB[n * 64 + c] : 0.f;
    }
    __syncthreads();
    int cg = t & 15, ng = t >> 4;
    float acc[8][4];
#pragma unroll
    for (int i = 0; i < 8; i++)
#pragma unroll
        for (int j = 0; j < 4; j++) acc[i][j] = 0.f;
#pragma unroll 8
    for (int k = 0; k < 64; k++) {
        float4 w4 = *(const float4*)&Ws[k][cg * 4];
#pragma unroll
        for (int i = 0; i < 8; i++) {
            float xv = xs[ng * 8 + i][k];
            acc[i][0] += xv * w4.x;
            acc[i][1] += xv * w4.y;
            acc[i][2] += xv * w4.z;
            acc[i][3] += xv * w4.w;
        }
    }
    // store fp16 mirror (only consumer is the next gather pass)
#pragma unroll
    for (int i = 0; i < 8; i++) {
        int n = n0 + ng * 8 + i;
        if (n < N) {
            __half2* hp = (__half2*)(g_h16 + n * 64 + cg * 4);
            hp[0] = __floats2half2_rn(acc[i][0], acc[i][1]);
            hp[1] = __floats2half2_rn(acc[i][2], acc[i][3]);
        }
    }
    // fused s/d dots: partials over this thread's 4 cols, reduce over 16 lanes
    float a0 = avs[cg * 4], a1 = avs[cg * 4 + 1], a2 = avs[cg * 4 + 2], a3 = avs[cg * 4 + 3];
    float d0 = avd[cg * 4], d1 = avd[cg * 4 + 1], d2 = avd[cg * 4 + 2], d3 = avd[cg * 4 + 3];
#pragma unroll
    for (int i = 0; i < 8; i++) {
        float ps = acc[i][0] * a0 + acc[i][1] * a1 + acc[i][2] * a2 + acc[i][3] * a3;
        float pd = acc[i][0] * d0 + acc[i][1] * d1 + acc[i][2] * d2 + acc[i][3] * d3;
#pragma unroll
        for (int o = 8; o >= 1; o >>= 1) {
            ps += __shfl_xor_sync(0xffffffffu, ps, o, 16);
            pd += __shfl_xor_sync(0xffffffffu, pd, o, 16);
        }
        if (cg == 0) {
            int n = n0 + ng * 8 + i;
            if (n < N) { g_s[n] = ps; g_d[n] = pd; }
        }
    }
}

// ---------------------------------------------------------------------------
// Final stage (reads g_hB): out1 = h @ out_w + out_b (4x5 register tile);
// vn run-length pooling (batch sorted). Block: 128 nodes, 128 threads.
// ---------------------------------------------------------------------------
__global__ void fin_last_kernel(const float* __restrict__ out_w,
                                const float* __restrict__ out_b,
                                const int* __restrict__ batch,
                                float* __restrict__ out1, int N) {
    __shared__ float hs[128][65];
    __shared__ float ow[64][20];
    __shared__ float ob[20];
    __shared__ int bsh[128];
    int t = threadIdx.x;
    int n0 = blockIdx.x * 128;
    for (int idx = t; idx < 64 * 20; idx += 128) ow[idx / 20][idx % 20] = out_w[idx];
    if (t < 20) ob[t] = out_b[t];
#pragma unroll
    for (int j = 0; j < 64; j++) {
        int idx = j * 128 + t;
        int nl = idx >> 6, c = idx & 63;
        int n = n0 + nl;
        hs[nl][c] = (n < N) ? g_hB[n * 64 + c] : 0.f;
    }
    {
        int n = n0 + t;
        bsh[t] = (n < N) ? batch[n] : -1;
    }
    __syncthreads();
    int ngq = t >> 2, cgq = t & 3;   // 32 node groups x 4 col groups
    float acc[4][5];
#pragma unroll
    for (int i = 0; i < 4; i++)
#pragma unroll
        for (int j = 0; j < 5; j++) acc[i][j] = ob[cgq * 5 + j];
#pragma unroll 8
    for (int k = 0; k < 64; k++) {
        float wv[5];
#pragma unroll
        for (int j = 0; j < 5; j++) wv[j] = ow[k][cgq * 5 + j];
#pragma unroll
        for (int i = 0; i < 4; i++) {
            float hv = hs[ngq * 4 + i][k];
#pragma unroll
            for (int j = 0; j < 5; j++) acc[i][j] += hv * wv[j];
        }
    }
#pragma unroll
    for (int i = 0; i < 4; i++) {
        int n = n0 + ngq * 4 + i;
        if (n < N) {
#pragma unroll
            for (int j = 0; j < 5; j++) out1[n * 20 + cgq * 5 + j] = acc[i][j];
        }
    }
    // vn pooling: threads 0..63 own one column each, run-length over block
    if (t < 64) {
        int nend = N - n0;
        if (nend > 128) nend = 128;
        if (nend > 0) {
            int curg = bsh[0];
            float run = 0.f;
            for (int nl = 0; nl < nend; nl++) {
                int g = bsh[nl];
                if (g != curg) {
                    atomicAdd(&g_vnsum[curg * 64 + t], run);
                    run = 0.f;
                    curg = g;
                }
                run += hs[nl][t];
            }
            atomicAdd(&g_vnsum[curg * 64 + t], run);
        }
    }
}

// ---------------------------------------------------------------------------
// Virtual-node MLP head: 4 layers on [8,64] -> [8,20]. One block.
// ---------------------------------------------------------------------------
__global__ void vn_mlp_kernel(const float* __restrict__ vn_emb0,
                              const float* __restrict__ w1, const float* __restrict__ bb1,
                              const float* __restrict__ w2, const float* __restrict__ bb2,
                              const float* __restrict__ w3, const float* __restrict__ bb3,
                              const float* __restrict__ w4, const float* __restrict__ bb4,
                              float* __restrict__ outvn) {
    __shared__ float a[NGROUP][64], tmp[NGROUP][64];
    int t = threadIdx.x;  // 512
    int g = t >> 6, c = t & 63;
    a[g][c] = g_vnsum[g * 64 + c] + vn_emb0[c];
    __syncthreads();
    float s = bb1[c];
    for (int k = 0; k < 64; k++) s += a[g][k] * w1[k * 64 + c];
    tmp[g][c] = fmaxf(s, 0.f);
    __syncthreads();
    s = bb2[c];
    for (int k = 0; k < 64; k++) s += tmp[g][k] * w2[k * 64 + c];
    a[g][c] = fmaxf(s, 0.f);
    __syncthreads();
    s = bb3[c];
    for (int k = 0; k < 64; k++) s += a[g][k] * w3[k * 64 + c];
    tmp[g][c] = fmaxf(s, 0.f);
    __syncthreads();
    if (c < 20) {
        s = bb4[c];
        for (int k = 0; k < 64; k++) s += tmp[g][k] * w4[k * 20 + c];
        outvn[g * 20 + c] = fmaxf(s, 0.f);
    }
}

// ---------------------------------------------------------------------------
extern "C" void kernel_launch(void* const* d_in, const int* in_sizes, int n_in,
                              void* d_out, int out_size) {
    const float* x      = (const float*)d_in[0];
    const int*   ei     = (const int*)d_in[1];
    const int*   batch  = (const int*)d_in[2];
    const float* W0     = (const float*)d_in[3];
    const float* as0    = (const float*)d_in[4];
    const float* ad0    = (const float*)d_in[5];
    const float* b0     = (const float*)d_in[6];
    const float* W1     = (const float*)d_in[7];
    const float* as1    = (const float*)d_in[8];
    const float* ad1    = (const float*)d_in[9];
    const float* b1     = (const float*)d_in[10];
    const float* W2     = (const float*)d_in[11];
    const float* as2    = (const float*)d_in[12];
    const float* ad2    = (const float*)d_in[13];
    const float* b2     = (const float*)d_in[14];
    const float* vn_emb0= (const float*)d_in[15];
    const float* m1_w1  = (const float*)d_in[16];
    const float* m1_b1  = (const float*)d_in[17];
    const float* m1_w2  = (const float*)d_in[18];
    const float* m1_b2  = (const float*)d_in[19];
    const float* mf_w1  = (const float*)d_in[20];
    const float* mf_b1  = (const float*)d_in[21];
    const float* mf_w2  = (const float*)d_in[22];
    const float* mf_b2  = (const float*)d_in[23];
    const float* out_w  = (const float*)d_in[24];
    const float* out_b  = (const float*)d_in[25];

    int N = in_sizes[0] / 3;
    int E = in_sizes[1] / 2;
    float* out1 = (float*)d_out;
    float* outvn = out1 + (long long)N * 20;

    int nblk64  = (N + 63) / 64;
    int nblk128 = (N + 127) / 128;
    int eblk    = (E + 255) / 256;
    int NB      = (N + 1023) / 1024;
    int gblk    = (N * 32 + 255) / 256;   // one full warp per node

    // CSR build (graph shared by all 3 layers)
    zero_kernel<<<(N + 256) / 256, 256>>>(N);
    hist_kernel<<<eblk, 256>>>(ei, E);
    scanA_kernel<<<NB, 256>>>(N);
    scanC_kernel<<<(N + 255) / 256, 256>>>(N, E);
    scatter_kernel<<<eblk, 256>>>(ei, E);

    // GNN layers (ping-pong: lin0 -> h16, gather h16->B, fin_lin B->h16)
    lin0_kernel<<<nblk64, 256>>>(x, W0, as0, ad0, N);
    gather_kernel<<<gblk, 256>>>(b0, N);
    fin_lin_kernel<<<nblk128, 256>>>(W1, as1, ad1, N);
    gather_kernel<<<gblk, 256>>>(b1, N);
    fin_lin_kernel<<<nblk128, 256>>>(W2, as2, ad2, N);
    gather_kernel<<<gblk, 256>>>(b2, N);

    // heads (read g_hB)
    fin_last_kernel<<<nblk128, 128>>>(out_w, out_b, batch, out1, N);
    vn_mlp_kernel<<<1, 512>>>(vn_emb0, m1_w1, m1_b1, m1_w2, m1_b2,
                              mf_w1, mf_b1, mf_w2, mf_b2, outvn);
}

// round 8
// speedup vs baseline: 1.7141x; 1.2490x over previous
#include <cuda_runtime.h>
#include <cuda_fp16.h>

#define NMAX 100000
#define EMAX 1600000
#define HDIM 64
#define NGROUP 8

// ---------------- device scratch (no allocation allowed) --------------------
__device__ __align__(256) __half g_h16[NMAX * HDIM];  // fp16 mirror for gathers
__device__ __align__(256) float g_hB[NMAX * HDIM];    // fp32 gather output
__device__ float g_s[NMAX];
__device__ float g_d[NMAX];
__device__ int   g_cnt[NMAX + 1];     // histogram, later scatter cursor
__device__ int   g_offs[NMAX + 1];    // CSR row offsets (by dst)
__device__ int   g_blksum[256];
__device__ int   g_csr[EMAX];         // src indices sorted by dst
__device__ float g_vnsum[NGROUP * HDIM];

// ---------------------------------------------------------------------------
// CSR build: zero -> histogram -> scanA -> scanC(+blk prefix) -> scatter
// ---------------------------------------------------------------------------
__global__ void zero_kernel(int N) {
    int i = blockIdx.x * blockDim.x + threadIdx.x;
    if (i <= N) g_cnt[i] = 0;
    if (i < NGROUP * HDIM) g_vnsum[i] = 0.f;
}

__global__ void hist_kernel(const int* __restrict__ ei, int E) {
    int e = blockIdx.x * blockDim.x + threadIdx.x;
    if (e < E) atomicAdd(&g_cnt[ei[E + e]], 1);
}

// per-block exclusive scan of g_cnt (1024 elements / block of 256 threads)
__global__ void scanA_kernel(int N) {
    __shared__ int wsum[8];
    int t = threadIdx.x;
    int base = blockIdx.x * 1024;
    int v[4]; int s = 0;
#pragma unroll
    for (int j = 0; j < 4; j++) {
        int idx = base + t * 4 + j;
        v[j] = (idx < N) ? g_cnt[idx] : 0;
        s += v[j];
    }
    int lane = t & 31, wid = t >> 5;
    int inc = s;
#pragma unroll
    for (int o = 1; o < 32; o <<= 1) {
        int y = __shfl_up_sync(0xffffffffu, inc, o);
        if (lane >= o) inc += y;
    }
    if (lane == 31) wsum[wid] = inc;
    __syncthreads();
    if (t < 8) {
        int x = wsum[t];
#pragma unroll
        for (int o = 1; o < 8; o <<= 1) {
            int y = __shfl_up_sync(0xffu, x, o);
            if (t >= o) x += y;
        }
        wsum[t] = x;
    }
    __syncthreads();
    int excl = inc - s + (wid > 0 ? wsum[wid - 1] : 0);
#pragma unroll
    for (int j = 0; j < 4; j++) {
        int idx = base + t * 4 + j;
        if (idx < N) g_offs[idx] = excl;
        excl += v[j];
    }
    if (t == 255) g_blksum[blockIdx.x] = wsum[7];
}

// adds cross-block prefix (computed in-kernel by warp 0) and finalizes offsets
__global__ void scanC_kernel(int N, int E) {
    __shared__ int sbase;
    int myblk = (blockIdx.x * 256) >> 10;   // which scanA block this belongs to
    if (threadIdx.x < 32) {
        int acc = 0;
        for (int j = threadIdx.x; j < myblk; j += 32) acc += g_blksum[j];
#pragma unroll
        for (int o = 16; o >= 1; o >>= 1) acc += __shfl_xor_sync(0xffffffffu, acc, o);
        if (threadIdx.x == 0) sbase = acc;
    }
    __syncthreads();
    int i = blockIdx.x * 256 + threadIdx.x;
    if (i < N) {
        int o = g_offs[i] + sbase;
        g_offs[i] = o;
        g_cnt[i] = o;   // scatter cursor
    }
    if (i == 0) g_offs[N] = E;
}

__global__ void scatter_kernel(const int* __restrict__ ei, int E) {
    int e = blockIdx.x * blockDim.x + threadIdx.x;
    if (e >= E) return;
    int src = ei[e];
    int dst = ei[E + e];
    int pos = atomicAdd(&g_cnt[dst], 1);
    g_csr[pos] = src;
}

// ---------------------------------------------------------------------------
// Layer 0 linear: h = x(N,3) @ W0(3,64) -> g_h16; also s = h.as, d = h.ad
// ---------------------------------------------------------------------------
__global__ void lin0_kernel(const float* __restrict__ x,
                            const float* __restrict__ W0,
                            const float* __restrict__ as0,
                            const float* __restrict__ ad0, int N) {
    __shared__ float Ws[3 * 64];
    __shared__ float hs[64][65];
    int t = threadIdx.x;
    int c = t & 63, r = t >> 6;
    int n0 = blockIdx.x * 64;
    if (t < 192) Ws[t] = W0[t];
    __syncthreads();
#pragma unroll
    for (int i = 0; i < 16; i++) {
        int nl = r * 16 + i;
        int n = n0 + nl;
        float acc = 0.f;
        if (n < N) {
            float x0 = x[n * 3 + 0], x1 = x[n * 3 + 1], x2 = x[n * 3 + 2];
            acc = x0 * Ws[c] + x1 * Ws[64 + c] + x2 * Ws[128 + c];
            g_h16[n * 64 + c] = __float2half_rn(acc);
        }
        hs[nl][c] = acc;
    }
    __syncthreads();
    if (t < 64) {
        int n = n0 + t;
        if (n < N) {
            float sv = 0.f, dv = 0.f;
#pragma unroll
            for (int k = 0; k < 64; k++) {
                float hv = hs[t][k];
                sv += hv * as0[k];
                dv += hv * ad0[k];
            }
            g_s[n] = sv;
            g_d[n] = dv;
        }
    }
}

// ---------------------------------------------------------------------------
// Gather attention pass (g_h16 -> g_hB): one warp per dst node.
// (exact copy of the 240.4us version: stage int2, inner unroll 4)
// (max-shift skipped: softmax shift-invariant, logits are O(0.1))
// ---------------------------------------------------------------------------
__global__ void gather_kernel(const float* __restrict__ bias, int N) {
    __shared__ int2 stage[8][32];
    int w = (blockIdx.x * blockDim.x + threadIdx.x) >> 5;
    int lane = threadIdx.x & 31;
    int wl = threadIdx.x >> 5;
    if (w >= N) return;
    int dst = w;
    float dv = g_d[dst];
    // self loop
    float lg = g_s[dst] + dv;
    lg = lg > 0.f ? lg : 0.2f * lg;
    float pself = __expf(lg);
    float2 h2 = __half22float2(*(const __half2*)(g_h16 + dst * 64 + lane * 2));
    float ax = pself * h2.x, ay = pself * h2.y;
    float denl = (lane == 0) ? pself : 0.f;
    int e0 = g_offs[dst], e1 = g_offs[dst + 1];
    for (int base = e0; base < e1; base += 32) {
        int cnt = e1 - base;
        if (cnt > 32) cnt = 32;
        int idx = 0;
        float pv = 0.f;
        if (lane < cnt) {
            idx = g_csr[base + lane];
            float sv = g_s[idx];
            float l = sv + dv;
            l = l > 0.f ? l : 0.2f * l;
            pv = __expf(l);
        }
        denl += pv;
        stage[wl][lane] = make_int2(idx, __float_as_int(pv));
        __syncwarp();
        int j = 0;
        for (; j + 3 < cnt; j += 4) {
            int2 v0 = stage[wl][j],     v1 = stage[wl][j + 1];
            int2 v2 = stage[wl][j + 2], v3 = stage[wl][j + 3];
            float2 f0 = __half22float2(*(const __half2*)(g_h16 + v0.x * 64 + lane * 2));
            float2 f1 = __half22float2(*(const __half2*)(g_h16 + v1.x * 64 + lane * 2));
            float2 f2 = __half22float2(*(const __half2*)(g_h16 + v2.x * 64 + lane * 2));
            float2 f3 = __half22float2(*(const __half2*)(g_h16 + v3.x * 64 + lane * 2));
            float p0 = __int_as_float(v0.y), p1 = __int_as_float(v1.y);
            float p2 = __int_as_float(v2.y), p3 = __int_as_float(v3.y);
            ax += p0 * f0.x + p1 * f1.x + p2 * f2.x + p3 * f3.x;
            ay += p0 * f0.y + p1 * f1.y + p2 * f2.y + p3 * f3.y;
        }
        for (; j < cnt; j++) {
            int2 v = stage[wl][j];
            float2 f = __half22float2(*(const __half2*)(g_h16 + v.x * 64 + lane * 2));
            float pj = __int_as_float(v.y);
            ax += pj * f.x;
            ay += pj * f.y;
        }
        __syncwarp();
    }
#pragma unroll
    for (int o = 16; o >= 1; o >>= 1) denl += __shfl_xor_sync(0xffffffffu, denl, o);
    float inv = 1.f / denl;
    float ox = ax * inv + bias[lane * 2];
    float oy = ay * inv + bias[lane * 2 + 1];
    ox = ox > 0.f ? ox : 0.01f * ox;
    oy = oy > 0.f ? oy : 0.01f * oy;
    *(float2*)(g_hB + dst * 64 + lane * 2) = make_float2(ox, oy);
}

// ---------------------------------------------------------------------------
// Tensor-core GEMM (g_hB -> g_h16): h = x(128,64) @ W(64,64) via
// mma.sync.m16n8k8.f32.f16.f16.f32. Block 256 = 8 warps x 16 nodes.
// Smem: xh[128][72] fp16 (A, row-major, 72-stride = conflict-free),
//       Wt[64][72] fp16 (W transposed -> B col-major fragments contiguous).
// s/d dots computed from fp32 accumulators (4-lane shuffle reduce).
// ---------------------------------------------------------------------------
__global__ void fin_lin_kernel(const float* __restrict__ W,
                               const float* __restrict__ avs,
                               const float* __restrict__ avd, int N) {
    __shared__ __half xh[128][72];
    __shared__ __half Wt[64][72];
    __shared__ float as_sh[64], ad_sh[64];
    int t = threadIdx.x;
    int n0 = blockIdx.x * 128;
    // W -> fp16 transposed
#pragma unroll
    for (int j = 0; j < 16; j++) {
        int idx = j * 256 + t;
        int k = idx >> 6, n = idx & 63;
        Wt[n][k] = __float2half_rn(W[idx]);
    }
    if (t < 64) { as_sh[t] = avs[t]; ad_sh[t] = avd[t]; }
    // x (fp32 gather output) -> fp16 smem
#pragma unroll
    for (int j = 0; j < 8; j++) {
        int idx = j * 256 + t;            // float4 chunks over 128x64
        int nl = idx >> 4, c4 = (idx & 15) * 4;
        int n = n0 + nl;
        float4 v = (n < N) ? *(const float4*)(g_hB + (long long)n * 64 + c4)
                           : make_float4(0.f, 0.f, 0.f, 0.f);
        *(__half2*)&xh[nl][c4]     = __floats2half2_rn(v.x, v.y);
        *(__half2*)&xh[nl][c4 + 2] = __floats2half2_rn(v.z, v.w);
    }
    __syncthreads();

    int wid = t >> 5, lane = t & 31;
    int g = lane >> 2, tg = lane & 3;
    int nw = wid * 16;                     // warp's node base within block
    float acc[8][4];
#pragma unroll
    for (int i = 0; i < 8; i++)
#pragma unroll
        for (int j = 0; j < 4; j++) acc[i][j] = 0.f;

#pragma unroll
    for (int s = 0; s < 8; s++) {
        unsigned a0 = *(const unsigned*)&xh[nw + g][s * 8 + tg * 2];
        unsigned a1 = *(const unsigned*)&xh[nw + g + 8][s * 8 + tg * 2];
#pragma unroll
        for (int nt = 0; nt < 8; nt++) {
            unsigned b = *(const unsigned*)&Wt[nt * 8 + g][s * 8 + tg * 2];
            asm volatile(
                "mma.sync.aligned.m16n8k8.row.col.f32.f16.f16.f32 "
                "{%0,%1,%2,%3}, {%4,%5}, {%6}, {%0,%1,%2,%3};"
                : "+f"(acc[nt][0]), "+f"(acc[nt][1]),
                  "+f"(acc[nt][2]), "+f"(acc[nt][3])
                : "r"(a0), "r"(a1), "r"(b));
        }
    }

    // s/d dots from fp32 accumulators: lane covers cols nt*8+tg*2(+1),
    // rows g and g+8; reduce partials over the 4 tg lanes.
    float ps0 = 0.f, ps1 = 0.f, pd0 = 0.f, pd1 = 0.f;
#pragma unroll
    for (int nt = 0; nt < 8; nt++) {
        float2 a = *(const float2*)&as_sh[nt * 8 + tg * 2];
        float2 d = *(const float2*)&ad_sh[nt * 8 + tg * 2];
        ps0 += acc[nt][0] * a.x + acc[nt][1] * a.y;
        ps1 += acc[nt][2] * a.x + acc[nt][3] * a.y;
        pd0 += acc[nt][0] * d.x + acc[nt][1] * d.y;
        pd1 += acc[nt][2] * d.x + acc[nt][3] * d.y;
    }
#pragma unroll
    for (int o = 1; o <= 2; o <<= 1) {
        ps0 += __shfl_xor_sync(0xffffffffu, ps0, o);
        ps1 += __shfl_xor_sync(0xffffffffu, ps1, o);
        pd0 += __shfl_xor_sync(0xffffffffu, pd0, o);
        pd1 += __shfl_xor_sync(0xffffffffu, pd1, o);
    }
    if (tg == 0) {
        int n1 = n0 + nw + g, n2 = n1 + 8;
        if (n1 < N) { g_s[n1] = ps0; g_d[n1] = pd0; }
        if (n2 < N) { g_s[n2] = ps1; g_d[n2] = pd1; }
    }

    // stage fp16 result into this warp's own xh rows, then vectorized copy out
#pragma unroll
    for (int nt = 0; nt < 8; nt++) {
        *(__half2*)&xh[nw + g][nt * 8 + tg * 2]     = __floats2half2_rn(acc[nt][0], acc[nt][1]);
        *(__half2*)&xh[nw + g + 8][nt * 8 + tg * 2] = __floats2half2_rn(acc[nt][2], acc[nt][3]);
    }
    __syncwarp();
#pragma unroll
    for (int j = 0; j < 4; j++) {
        int cid = j * 32 + lane;           // 128 uint4 chunks = 16 rows x 8
        int r = nw + (cid >> 3);
        int c = (cid & 7) * 8;
        uint4 v = *(const uint4*)&xh[r][c];
        int n = n0 + r;
        if (n < N) *(uint4*)(g_h16 + (long long)n * 64 + c) = v;
    }
}

// ---------------------------------------------------------------------------
// Final stage (reads g_hB): out1 = h @ out_w + out_b (4x5 register tile);
// vn run-length pooling (batch sorted). Block: 128 nodes, 128 threads.
// ---------------------------------------------------------------------------
__global__ void fin_last_kernel(const float* __restrict__ out_w,
                                const float* __restrict__ out_b,
                                const int* __restrict__ batch,
                                float* __restrict__ out1, int N) {
    __shared__ float hs[128][65];
    __shared__ float ow[64][20];
    __shared__ float ob[20];
    __shared__ int bsh[128];
    int t = threadIdx.x;
    int n0 = blockIdx.x * 128;
    for (int idx = t; idx < 64 * 20; idx += 128) ow[idx / 20][idx % 20] = out_w[idx];
    if (t < 20) ob[t] = out_b[t];
#pragma unroll
    for (int j = 0; j < 64; j++) {
        int idx = j * 128 + t;
        int nl = idx >> 6, c = idx & 63;
        int n = n0 + nl;
        hs[nl][c] = (n < N) ? g_hB[n * 64 + c] : 0.f;
    }
    {
        int n = n0 + t;
        bsh[t] = (n < N) ? batch[n] : -1;
    }
    __syncthreads();
    int ngq = t >> 2, cgq = t & 3;   // 32 node groups x 4 col groups
    float acc[4][5];
#pragma unroll
    for (int i = 0; i < 4; i++)
#pragma unroll
        for (int j = 0; j < 5; j++) acc[i][j] = ob[cgq * 5 + j];
#pragma unroll 8
    for (int k = 0; k < 64; k++) {
        float wv[5];
#pragma unroll
        for (int j = 0; j < 5; j++) wv[j] = ow[k][cgq * 5 + j];
#pragma unroll
        for (int i = 0; i < 4; i++) {
            float hv = hs[ngq * 4 + i][k];
#pragma unroll
            for (int j = 0; j < 5; j++) acc[i][j] += hv * wv[j];
        }
    }
#pragma unroll
    for (int i = 0; i < 4; i++) {
        int n = n0 + ngq * 4 + i;
        if (n < N) {
#pragma unroll
            for (int j = 0; j < 5; j++) out1[n * 20 + cgq * 5 + j] = acc[i][j];
        }
    }
    // vn pooling: threads 0..63 own one column each, run-length over block
    if (t < 64) {
        int nend = N - n0;
        if (nend > 128) nend = 128;
        if (nend > 0) {
            int curg = bsh[0];
            float run = 0.f;
            for (int nl = 0; nl < nend; nl++) {
                int g = bsh[nl];
                if (g != curg) {
                    atomicAdd(&g_vnsum[curg * 64 + t], run);
                    run = 0.f;
                    curg = g;
                }
                run += hs[nl][t];
            }
            atomicAdd(&g_vnsum[curg * 64 + t], run);
        }
    }
}

// ---------------------------------------------------------------------------
// Virtual-node MLP head: 4 layers on [8,64] -> [8,20]. One block.
// ---------------------------------------------------------------------------
__global__ void vn_mlp_kernel(const float* __restrict__ vn_emb0,
                              const float* __restrict__ w1, const float* __restrict__ bb1,
                              const float* __restrict__ w2, const float* __restrict__ bb2,
                              const float* __restrict__ w3, const float* __restrict__ bb3,
                              const float* __restrict__ w4, const float* __restrict__ bb4,
                              float* __restrict__ outvn) {
    __shared__ float a[NGROUP][64], tmp[NGROUP][64];
    int t = threadIdx.x;  // 512
    int g = t >> 6, c = t & 63;
    a[g][c] = g_vnsum[g * 64 + c] + vn_emb0[c];
    __syncthreads();
    float s = bb1[c];
    for (int k = 0; k < 64; k++) s += a[g][k] * w1[k * 64 + c];
    tmp[g][c] = fmaxf(s, 0.f);
    __syncthreads();
    s = bb2[c];
    for (int k = 0; k < 64; k++) s += tmp[g][k] * w2[k * 64 + c];
    a[g][c] = fmaxf(s, 0.f);
    __syncthreads();
    s = bb3[c];
    for (int k = 0; k < 64; k++) s += a[g][k] * w3[k * 64 + c];
    tmp[g][c] = fmaxf(s, 0.f);
    __syncthreads();
    if (c < 20) {
        s = bb4[c];
        for (int k = 0; k < 64; k++) s += tmp[g][k] * w4[k * 20 + c];
        outvn[g * 20 + c] = fmaxf(s, 0.f);
    }
}

// ---------------------------------------------------------------------------
extern "C" void kernel_launch(void* const* d_in, const int* in_sizes, int n_in,
                              void* d_out, int out_size) {
    const float* x      = (const float*)d_in[0];
    const int*   ei     = (const int*)d_in[1];
    const int*   batch  = (const int*)d_in[2];
    const float* W0     = (const float*)d_in[3];
    const float* as0    = (const float*)d_in[4];
    const float* ad0    = (const float*)d_in[5];
    const float* b0     = (const float*)d_in[6];
    const float* W1     = (const float*)d_in[7];
    const float* as1    = (const float*)d_in[8];
    const float* ad1    = (const float*)d_in[9];
    const float* b1     = (const float*)d_in[10];
    const float* W2     = (const float*)d_in[11];
    const float* as2    = (const float*)d_in[12];
    const float* ad2    = (const float*)d_in[13];
    const float* b2     = (const float*)d_in[14];
    const float* vn_emb0= (const float*)d_in[15];
    const float* m1_w1  = (const float*)d_in[16];
    const float* m1_b1  = (const float*)d_in[17];
    const float* m1_w2  = (const float*)d_in[18];
    const float* m1_b2  = (const float*)d_in[19];
    const float* mf_w1  = (const float*)d_in[20];
    const float* mf_b1  = (const float*)d_in[21];
    const float* mf_w2  = (const float*)d_in[22];
    const float* mf_b2  = (const float*)d_in[23];
    const float* out_w  = (const float*)d_in[24];
    const float* out_b  = (const float*)d_in[25];

    int N = in_sizes[0] / 3;
    int E = in_sizes[1] / 2;
    float* out1 = (float*)d_out;
    float* outvn = out1 + (long long)N * 20;

    int nblk64  = (N + 63) / 64;
    int nblk128 = (N + 127) / 128;
    int eblk    = (E + 255) / 256;
    int NB      = (N + 1023) / 1024;
    int gblk    = (N * 32 + 255) / 256;   // one full warp per node

    // CSR build (graph shared by all 3 layers)
    zero_kernel<<<(N + 256) / 256, 256>>>(N);
    hist_kernel<<<eblk, 256>>>(ei, E);
    scanA_kernel<<<NB, 256>>>(N);
    scanC_kernel<<<(N + 255) / 256, 256>>>(N, E);
    scatter_kernel<<<eblk, 256>>>(ei, E);

    // GNN layers (ping-pong: lin0 -> h16, gather h16->B, fin_lin B->h16)
    lin0_kernel<<<nblk64, 256>>>(x, W0, as0, ad0, N);
    gather_kernel<<<gblk, 256>>>(b0, N);
    fin_lin_kernel<<<nblk128, 256>>>(W1, as1, ad1, N);
    gather_kernel<<<gblk, 256>>>(b1, N);
    fin_lin_kernel<<<nblk128, 256>>>(W2, as2, ad2, N);
    gather_kernel<<<gblk, 256>>>(b2, N);

    // heads (read g_hB)
    fin_last_kernel<<<nblk128, 128>>>(out_w, out_b, batch, out1, N);
    vn_mlp_kernel<<<1, 512>>>(vn_emb0, m1_w1, m1_b1, m1_w2, m1_b2,
                              mf_w1, mf_b1, mf_w2, mf_b2, outvn);
}